// round 9
// baseline (speedup 1.0000x reference)
#include <cuda_runtime.h>
#include <cuda_bf16.h>
#include <cstdint>

// BiGRU: B=64, S=4096, D_in=7, H=128, 2 layers, bidirectional, fp32.
//   k_gx0    : gx0 = x @ Wih0^T + bih0 (both dirs)     -> g_gx [tok][768]
//   k_rec    : per-(batch,dir) recurrence; 128 thr, thread owns ALL 3 gate
//              rows of one h-index -> zero exchange, 1 barrier/step
//   k_gemm_tc: gx1 = h1in @ Wih1^T + bih1 (R6-validated single-buffer mma.sync)
//   k_rec    : layer 1
//   k_head   : logits = h1out @ wout^T + bout

#define BB   64
#define SS   4096
#define DIN  7
#define HH   128
#define G3   384
#define NTOK (BB * SS)          // 262144

// ---------------- scratch (device globals; reused across phases) -------------
__device__ float g_gx [ (size_t)NTOK * 768 ];   // gate pre-activations [f384|b384]
__device__ float g_hio[ (size_t)NTOK * 256 ];   // layer in/out hidden  [f128|b128]

// ---------------- f32x2 helpers ----------------------------------------------
__device__ __forceinline__ unsigned long long ffma2(unsigned long long a,
                                                    unsigned long long b,
                                                    unsigned long long c) {
    unsigned long long d;
    asm("fma.rn.f32x2 %0, %1, %2, %3;" : "=l"(d) : "l"(a), "l"(b), "l"(c));
    return d;
}
__device__ __forceinline__ float2 unpk(unsigned long long v) {
    float2 r;
    asm("mov.b64 {%0, %1}, %2;" : "=f"(r.x), "=f"(r.y) : "l"(v));
    return r;
}
__device__ __forceinline__ float sigf(float x) {
    return __fdividef(1.f, 1.f + __expf(-x));
}
__device__ __forceinline__ float tanhfast(float x) {
    return 1.f - __fdividef(2.f, __expf(2.f * x) + 1.f);
}

// ---------------- warp-MMA helpers (baseline PTX, sm_80+) ---------------------
__device__ __forceinline__ uint32_t smem_u32(const void* p) {
    uint32_t a;
    asm("{ .reg .u64 t; cvta.to.shared.u64 t, %1; cvt.u32.u64 %0, t; }"
        : "=r"(a) : "l"(p));
    return a;
}
__device__ __forceinline__ void ldmx4(uint32_t& r0, uint32_t& r1,
                                      uint32_t& r2, uint32_t& r3, uint32_t addr) {
    asm volatile("ldmatrix.sync.aligned.m8n8.x4.shared.b16 {%0,%1,%2,%3}, [%4];"
                 : "=r"(r0), "=r"(r1), "=r"(r2), "=r"(r3) : "r"(addr));
}
__device__ __forceinline__ void mma_bf16(float* d, const uint32_t* a,
                                         const uint32_t* b) {
    asm volatile("mma.sync.aligned.m16n8k16.row.col.f32.bf16.bf16.f32 "
                 "{%0,%1,%2,%3}, {%4,%5,%6,%7}, {%8,%9}, {%0,%1,%2,%3};"
                 : "+f"(d[0]), "+f"(d[1]), "+f"(d[2]), "+f"(d[3])
                 : "r"(a[0]), "r"(a[1]), "r"(a[2]), "r"(a[3]),
                   "r"(b[0]), "r"(b[1]));
}

// ---------------- layer-0 input projection (K=7) ------------------------------
__global__ void k_gx0(const float* __restrict__ x,
                      const float* __restrict__ wf, const float* __restrict__ bf,
                      const float* __restrict__ wb, const float* __restrict__ bb) {
    __shared__ float sx[8 * DIN];
    int j = threadIdx.x;                       // 0..767
    long long token0 = (long long)blockIdx.x * 8;
    int dir = (j >= G3);
    int jj = dir ? j - G3 : j;
    const float* wrow = (dir ? wb : wf) + jj * DIN;
    float w0 = wrow[0], w1 = wrow[1], w2 = wrow[2], w3 = wrow[3];
    float w4 = wrow[4], w5 = wrow[5], w6 = wrow[6];
    float bias = (dir ? bb : bf)[jj];
    if (j < 8 * DIN) sx[j] = x[token0 * DIN + j];
    __syncthreads();
#pragma unroll
    for (int tk = 0; tk < 8; tk++) {
        const float* xs = sx + tk * DIN;
        float v = bias;
        v = fmaf(w0, xs[0], v); v = fmaf(w1, xs[1], v); v = fmaf(w2, xs[2], v);
        v = fmaf(w3, xs[3], v); v = fmaf(w4, xs[4], v); v = fmaf(w5, xs[5], v);
        v = fmaf(w6, xs[6], v);
        g_gx[(token0 + tk) * 768 + j] = v;
    }
}

// ---------------- recurrence: 128 threads, zero-exchange ----------------------
// Thread j owns gate rows j (r), j+128 (z), j+256 (n): 384 weights = 192 regs.
// Per step: 32 LDS.128 of h (each reused by 3 rows), 192 FFMA2 in 6 chains,
// gates computed locally, h double-buffered in smem -> ONE barrier per step.
__global__ void __launch_bounds__(128, 1) k_rec(
    const float* __restrict__ whh_f, const float* __restrict__ bhh_f,
    const float* __restrict__ whh_b, const float* __restrict__ bhh_b) {
    __shared__ __align__(16) float s_h[2][HH];

    int j   = threadIdx.x;                     // 0..127
    int b   = blockIdx.x >> 1;
    int dir = blockIdx.x & 1;

    const float* whh  = dir ? whh_b : whh_f;
    const float* bhhp = dir ? bhh_b : bhh_f;

    // weights: rows j, j+128, j+256 (full 128 cols each) = 96 u64 regs
    unsigned long long wr[64], wz[64], wn[64];
    {
        const unsigned long long* p0 =
            (const unsigned long long*)(whh + (size_t)j * HH);
        const unsigned long long* p1 =
            (const unsigned long long*)(whh + (size_t)(j + HH) * HH);
        const unsigned long long* p2 =
            (const unsigned long long*)(whh + (size_t)(j + 2 * HH) * HH);
#pragma unroll
        for (int i = 0; i < 64; i++) { wr[i] = p0[i]; wz[i] = p1[i]; wn[i] = p2[i]; }
    }
    float br = bhhp[j], bz = bhhp[HH + j], bn = bhhp[2 * HH + j];

    long long tokbase = (long long)b * SS;
    int t0 = dir ? (SS - 1) : 0;
    long long gstr = dir ? -768 : 768;
    long long hstr = dir ? -256 : 256;

    const float* gp = g_gx + (tokbase + t0) * 768 + (long long)dir * G3 + j;
    float*       hp = g_hio + (tokbase + t0) * 256 + (long long)dir * HH + j;

    // 2-step-ahead gx prefetch (3 values per step)
    float xr1 = gp[0], xz1 = gp[HH], xn1 = gp[2 * HH];
    gp += gstr;
    float xr2 = gp[0], xz2 = gp[HH], xn2 = gp[2 * HH];

    s_h[0][j] = 0.f;
    float hreg = 0.f;
    __syncthreads();

    for (int tt = 0; tt < SS; tt++) {
        float xr = xr1, xz = xz1, xn = xn1;
        xr1 = xr2; xz1 = xz2; xn1 = xn2;
        gp += gstr;
        if (tt + 2 < SS) { xr2 = gp[0]; xz2 = gp[HH]; xn2 = gp[2 * HH]; }

        // ---- 3 dot products, 6 chains, shared h loads ----
        unsigned long long ar0 = 0ull, ar1 = 0ull;
        unsigned long long az0 = 0ull, az1 = 0ull;
        unsigned long long an0 = 0ull, an1 = 0ull;
        const ulonglong2* hv = (const ulonglong2*)s_h[tt & 1];
#pragma unroll
        for (int k = 0; k < 32; k++) {
            ulonglong2 hk = hv[k];              // LDS.128, broadcast; reused 3x
            ar0 = ffma2(wr[2 * k], hk.x, ar0); ar1 = ffma2(wr[2 * k + 1], hk.y, ar1);
            az0 = ffma2(wz[2 * k], hk.x, az0); az1 = ffma2(wz[2 * k + 1], hk.y, az1);
            an0 = ffma2(wn[2 * k], hk.x, an0); an1 = ffma2(wn[2 * k + 1], hk.y, an1);
        }
        float2 r0 = unpk(ar0), r1 = unpk(ar1);
        float2 z0 = unpk(az0), z1 = unpk(az1);
        float2 n0 = unpk(an0), n1 = unpk(an1);

        float r  = sigf((r0.x + r0.y) + (r1.x + r1.y) + br + xr);
        float z  = sigf((z0.x + z0.y) + (z1.x + z1.y) + bz + xz);
        float hn = (n0.x + n0.y) + (n1.x + n1.y) + bn;
        float n  = tanhfast(fmaf(r, hn, xn));
        hreg = fmaf(z, hreg - n, n);             // (1-z)*n + z*h

        s_h[(tt + 1) & 1][j] = hreg;             // write other bank: no RAW hazard
        *hp = hreg;
        hp += hstr;
        __syncthreads();                         // single barrier per step
    }
}

// ---------------- layer-1 GEMM via mma.sync (bf16 3-term split) ----------------
// R6-validated single-buffer version. C[262144x768] = A[262144x256]*W^T + bias.
// CTA tile M=128, N=256 (grid.y = 3), 8 warps as 2x4 (warp tile 64x64),
// K in 16 chunks of 16. acc += Ah*Bh + Ah*Bl + Al*Bh (fp32 accumulate).
#define ASTR 24          // smem row stride in bf16 elems (48B: aligned, no conflicts)

__global__ void __launch_bounds__(256, 1) k_gemm_tc(
    const float* __restrict__ Wf, const float* __restrict__ bf,
    const float* __restrict__ Wb, const float* __restrict__ bb) {
    __shared__ __align__(16) __nv_bfloat16 Ah[128][ASTR];
    __shared__ __align__(16) __nv_bfloat16 Al[128][ASTR];
    __shared__ __align__(16) __nv_bfloat16 Bh[256][ASTR];
    __shared__ __align__(16) __nv_bfloat16 Bl[256][ASTR];

    int tid = threadIdx.x, wid = tid >> 5, lane = tid & 31;
    long long m0 = (long long)blockIdx.x * 128;
    int n0 = blockIdx.y * 256;
    int wm = wid >> 2, wn = wid & 3;             // warp 64x64 tile at (wm*64, wn*64)

    uint32_t aoff = (uint32_t)(((wm * 64 + (lane & 15)) * ASTR + (lane >> 4) * 8) * 2);
    uint32_t boff = (uint32_t)(((wn * 64 + (lane & 7) + ((lane >> 4) << 3)) * ASTR
                                + ((lane >> 3) & 1) * 8) * 2);
    uint32_t ah_a = smem_u32(Ah) + aoff, al_a = smem_u32(Al) + aoff;
    uint32_t bh_a = smem_u32(Bh) + boff, bl_a = smem_u32(Bl) + boff;

    float acc[4][8][4];
#pragma unroll
    for (int i = 0; i < 4; i++)
#pragma unroll
        for (int jx = 0; jx < 8; jx++)
#pragma unroll
            for (int q = 0; q < 4; q++) acc[i][jx][q] = 0.f;

    float4 pA[2], pB[4];
#pragma unroll
    for (int i = 0; i < 2; i++) {
        int task = tid + i * 256, row = task >> 2, c4 = task & 3;
        pA[i] = *(const float4*)(g_hio + (m0 + row) * 256 + c4 * 4);
    }
#pragma unroll
    for (int i = 0; i < 4; i++) {
        int task = tid + i * 256, row = task >> 2, c4 = task & 3;
        int n = n0 + row;
        const float* src = (n < 384) ? (Wf + (size_t)n * 256)
                                     : (Wb + (size_t)(n - 384) * 256);
        pB[i] = *(const float4*)(src + c4 * 4);
    }

    for (int ck = 0; ck < 16; ck++) {
#pragma unroll
        for (int i = 0; i < 2; i++) {
            int task = tid + i * 256, row = task >> 2, c4 = task & 3;
            float4 v = pA[i];
            __nv_bfloat16 hx = __float2bfloat16(v.x), hy = __float2bfloat16(v.y);
            __nv_bfloat16 hz = __float2bfloat16(v.z), hw = __float2bfloat16(v.w);
            __nv_bfloat162 h01 = __halves2bfloat162(hx, hy);
            __nv_bfloat162 h23 = __halves2bfloat162(hz, hw);
            __nv_bfloat162 l01 = __halves2bfloat162(
                __float2bfloat16(v.x - __bfloat162float(hx)),
                __float2bfloat16(v.y - __bfloat162float(hy)));
            __nv_bfloat162 l23 = __halves2bfloat162(
                __float2bfloat16(v.z - __bfloat162float(hz)),
                __float2bfloat16(v.w - __bfloat162float(hw)));
            *(uint2*)&Ah[row][c4 * 4] = make_uint2(*(uint32_t*)&h01, *(uint32_t*)&h23);
            *(uint2*)&Al[row][c4 * 4] = make_uint2(*(uint32_t*)&l01, *(uint32_t*)&l23);
        }
#pragma unroll
        for (int i = 0; i < 4; i++) {
            int task = tid + i * 256, row = task >> 2, c4 = task & 3;
            float4 v = pB[i];
            __nv_bfloat16 hx = __float2bfloat16(v.x), hy = __float2bfloat16(v.y);
            __nv_bfloat16 hz = __float2bfloat16(v.z), hw = __float2bfloat16(v.w);
            __nv_bfloat162 h01 = __halves2bfloat162(hx, hy);
            __nv_bfloat162 h23 = __halves2bfloat162(hz, hw);
            __nv_bfloat162 l01 = __halves2bfloat162(
                __float2bfloat16(v.x - __bfloat162float(hx)),
                __float2bfloat16(v.y - __bfloat162float(hy)));
            __nv_bfloat162 l23 = __halves2bfloat162(
                __float2bfloat16(v.z - __bfloat162float(hz)),
                __float2bfloat16(v.w - __bfloat162float(hw)));
            *(uint2*)&Bh[row][c4 * 4] = make_uint2(*(uint32_t*)&h01, *(uint32_t*)&h23);
            *(uint2*)&Bl[row][c4 * 4] = make_uint2(*(uint32_t*)&l01, *(uint32_t*)&l23);
        }
        __syncthreads();

        if (ck + 1 < 16) {
            int kc = (ck + 1) * 16;
#pragma unroll
            for (int i = 0; i < 2; i++) {
                int task = tid + i * 256, row = task >> 2, c4 = task & 3;
                pA[i] = *(const float4*)(g_hio + (m0 + row) * 256 + kc + c4 * 4);
            }
#pragma unroll
            for (int i = 0; i < 4; i++) {
                int task = tid + i * 256, row = task >> 2, c4 = task & 3;
                int n = n0 + row;
                const float* src = (n < 384) ? (Wf + (size_t)n * 256)
                                             : (Wb + (size_t)(n - 384) * 256);
                pB[i] = *(const float4*)(src + kc + c4 * 4);
            }
        }

#pragma unroll
        for (int term = 0; term < 3; term++) {
            uint32_t aAddr = (term == 2) ? al_a : ah_a;
            uint32_t bAddr = (term == 1) ? bl_a : bh_a;
            uint32_t afr[4][4];
#pragma unroll
            for (int mf = 0; mf < 4; mf++)
                ldmx4(afr[mf][0], afr[mf][1], afr[mf][2], afr[mf][3],
                      aAddr + mf * (16 * ASTR * 2));
            uint32_t bfr[8][2];
#pragma unroll
            for (int p = 0; p < 4; p++) {
                uint32_t r0, r1, r2, r3;
                ldmx4(r0, r1, r2, r3, bAddr + p * (16 * ASTR * 2));
                bfr[2 * p][0] = r0; bfr[2 * p][1] = r1;
                bfr[2 * p + 1][0] = r2; bfr[2 * p + 1][1] = r3;
            }
#pragma unroll
            for (int mf = 0; mf < 4; mf++)
#pragma unroll
                for (int nf = 0; nf < 8; nf++)
                    mma_bf16(acc[mf][nf], afr[mf], bfr[nf]);
        }
        __syncthreads();
    }

    int g = lane >> 2, c2 = (lane & 3) * 2;
    float bias2[8][2];
#pragma unroll
    for (int nf = 0; nf < 8; nf++) {
        int col = n0 + wn * 64 + nf * 8 + c2;
        bias2[nf][0] = (col < 384) ? bf[col] : bb[col - 384];
        bias2[nf][1] = (col + 1 < 384) ? bf[col + 1] : bb[col + 1 - 384];
    }
#pragma unroll
    for (int mf = 0; mf < 4; mf++) {
        long long r0 = m0 + wm * 64 + mf * 16 + g;
#pragma unroll
        for (int nf = 0; nf < 8; nf++) {
            int col = n0 + wn * 64 + nf * 8 + c2;
            *(float2*)&g_gx[r0 * 768 + col] =
                make_float2(acc[mf][nf][0] + bias2[nf][0],
                            acc[mf][nf][1] + bias2[nf][1]);
            *(float2*)&g_gx[(r0 + 8) * 768 + col] =
                make_float2(acc[mf][nf][2] + bias2[nf][0],
                            acc[mf][nf][3] + bias2[nf][1]);
        }
    }
}

// ---------------- output head: logits = h1out @ wout^T + bout -----------------
__global__ void k_head(const float* __restrict__ wout,
                       const float* __restrict__ bout,
                       float* __restrict__ out) {
    int warp = threadIdx.x >> 5, lane = threadIdx.x & 31;
    long long token = (long long)blockIdx.x * 8 + warp;
    const float* hrow = g_hio + token * 256;
    float acc = 0.f;
#pragma unroll
    for (int i = 0; i < 8; i++) {
        int c = lane + i * 32;
        acc = fmaf(hrow[c], wout[c], acc);
    }
#pragma unroll
    for (int off = 16; off; off >>= 1)
        acc += __shfl_xor_sync(0xffffffffu, acc, off);
    if (lane == 0) out[token] = acc + bout[0];
}

// ---------------- launch ------------------------------------------------------
extern "C" void kernel_launch(void* const* d_in, const int* in_sizes, int n_in,
                              void* d_out, int out_size) {
    const float* x     = (const float*)d_in[0];
    const float* wih0f = (const float*)d_in[1];
    const float* whh0f = (const float*)d_in[2];
    const float* bih0f = (const float*)d_in[3];
    const float* bhh0f = (const float*)d_in[4];
    const float* wih0b = (const float*)d_in[5];
    const float* whh0b = (const float*)d_in[6];
    const float* bih0b = (const float*)d_in[7];
    const float* bhh0b = (const float*)d_in[8];
    const float* wih1f = (const float*)d_in[9];
    const float* whh1f = (const float*)d_in[10];
    const float* bih1f = (const float*)d_in[11];
    const float* bhh1f = (const float*)d_in[12];
    const float* wih1b = (const float*)d_in[13];
    const float* whh1b = (const float*)d_in[14];
    const float* bih1b = (const float*)d_in[15];
    const float* bhh1b = (const float*)d_in[16];
    const float* wout  = (const float*)d_in[17];
    const float* bout  = (const float*)d_in[18];
    float* out = (float*)d_out;

    k_gx0    <<<NTOK / 8, 768>>>(x, wih0f, bih0f, wih0b, bih0b);
    k_rec    <<<128, 128>>>(whh0f, bhh0f, whh0b, bhh0b);
    k_gemm_tc<<<dim3(2048, 3), 256>>>(wih1f, bih1f, wih1b, bih1b);
    k_rec    <<<128, 128>>>(whh1f, bhh1f, whh1b, bhh1b);
    k_head   <<<NTOK / 8, 256>>>(wout, bout, out);
}

// round 10
// speedup vs baseline: 2.7757x; 2.7757x over previous
#include <cuda_runtime.h>
#include <cuda_bf16.h>
#include <cstdint>

// BiGRU: B=64, S=4096, D_in=7, H=128, 2 layers, bidirectional, fp32.
//   k_gx0    : gx0 = x @ Wih0^T + bih0 (both dirs)     -> g_gx [tok][768]
//   k_rec    : R6-validated recurrence + asymmetric named barriers
//   k_gemm_tc: gx1 = h1in @ Wih1^T + bih1 (R6-validated mma.sync bf16 split)
//   k_rec    : layer 1
//   k_head   : logits = h1out @ wout^T + bout

#define BB   64
#define SS   4096
#define DIN  7
#define HH   128
#define G3   384
#define NTOK (BB * SS)          // 262144

// ---------------- scratch (device globals; reused across phases) -------------
__device__ float g_gx [ (size_t)NTOK * 768 ];   // gate pre-activations [f384|b384]
__device__ float g_hio[ (size_t)NTOK * 256 ];   // layer in/out hidden  [f128|b128]

// ---------------- f32x2 helpers ----------------------------------------------
__device__ __forceinline__ unsigned long long ffma2(unsigned long long a,
                                                    unsigned long long b,
                                                    unsigned long long c) {
    unsigned long long d;
    asm("fma.rn.f32x2 %0, %1, %2, %3;" : "=l"(d) : "l"(a), "l"(b), "l"(c));
    return d;
}
__device__ __forceinline__ float2 unpk(unsigned long long v) {
    float2 r;
    asm("mov.b64 {%0, %1}, %2;" : "=f"(r.x), "=f"(r.y) : "l"(v));
    return r;
}
__device__ __forceinline__ float sigf(float x) {
    return __fdividef(1.f, 1.f + __expf(-x));
}
__device__ __forceinline__ float tanhfast(float x) {
    return 1.f - __fdividef(2.f, __expf(2.f * x) + 1.f);
}

// ---------------- warp-MMA helpers (baseline PTX, sm_80+) ---------------------
__device__ __forceinline__ uint32_t smem_u32(const void* p) {
    uint32_t a;
    asm("{ .reg .u64 t; cvta.to.shared.u64 t, %1; cvt.u32.u64 %0, t; }"
        : "=r"(a) : "l"(p));
    return a;
}
__device__ __forceinline__ void ldmx4(uint32_t& r0, uint32_t& r1,
                                      uint32_t& r2, uint32_t& r3, uint32_t addr) {
    asm volatile("ldmatrix.sync.aligned.m8n8.x4.shared.b16 {%0,%1,%2,%3}, [%4];"
                 : "=r"(r0), "=r"(r1), "=r"(r2), "=r"(r3) : "r"(addr));
}
__device__ __forceinline__ void mma_bf16(float* d, const uint32_t* a,
                                         const uint32_t* b) {
    asm volatile("mma.sync.aligned.m16n8k16.row.col.f32.bf16.bf16.f32 "
                 "{%0,%1,%2,%3}, {%4,%5,%6,%7}, {%8,%9}, {%0,%1,%2,%3};"
                 : "+f"(d[0]), "+f"(d[1]), "+f"(d[2]), "+f"(d[3])
                 : "r"(a[0]), "r"(a[1]), "r"(a[2]), "r"(a[3]),
                   "r"(b[0]), "r"(b[1]));
}

// ---------------- layer-0 input projection (K=7) ------------------------------
__global__ void k_gx0(const float* __restrict__ x,
                      const float* __restrict__ wf, const float* __restrict__ bf,
                      const float* __restrict__ wb, const float* __restrict__ bb) {
    __shared__ float sx[8 * DIN];
    int j = threadIdx.x;                       // 0..767
    long long token0 = (long long)blockIdx.x * 8;
    int dir = (j >= G3);
    int jj = dir ? j - G3 : j;
    const float* wrow = (dir ? wb : wf) + jj * DIN;
    float w0 = wrow[0], w1 = wrow[1], w2 = wrow[2], w3 = wrow[3];
    float w4 = wrow[4], w5 = wrow[5], w6 = wrow[6];
    float bias = (dir ? bb : bf)[jj];
    if (j < 8 * DIN) sx[j] = x[token0 * DIN + j];
    __syncthreads();
#pragma unroll
    for (int tk = 0; tk < 8; tk++) {
        const float* xs = sx + tk * DIN;
        float v = bias;
        v = fmaf(w0, xs[0], v); v = fmaf(w1, xs[1], v); v = fmaf(w2, xs[2], v);
        v = fmaf(w3, xs[3], v); v = fmaf(w4, xs[4], v); v = fmaf(w5, xs[5], v);
        v = fmaf(w6, xs[6], v);
        g_gx[(token0 + tk) * 768 + j] = v;
    }
}

// ---------------- recurrence (R6 skeleton + asymmetric named barriers) --------
// 384 threads; thread j owns gate-row j (64 f32x2 weight regs).
// Producer/consumer barrier split:
//   non-gate warps (4-11): bar.arrive 1 ; bar.sync 2   (block once per step)
//   gate warps     (0-3) : bar.sync 1 ; gates ; STS h ;
//                          bar.sync 3 (128, gate-internal) ; bar.arrive 2 ;
//                          STG h off-path ; next burst without blocking.
__global__ void __launch_bounds__(384, 1) k_rec(
    const float* __restrict__ whh_f, const float* __restrict__ bhh_f,
    const float* __restrict__ whh_b, const float* __restrict__ bhh_b) {
    __shared__ __align__(16) float s_h[HH];
    __shared__ float s_b[G3];
    __shared__ float s_xn[HH];

    int j   = threadIdx.x;
    int b   = blockIdx.x >> 1;
    int dir = blockIdx.x & 1;

    const float* whh = dir ? whh_b : whh_f;
    float bhh = (dir ? bhh_b : bhh_f)[j];

    unsigned long long w[64];
    const unsigned long long* wp =
        (const unsigned long long*)(whh + (size_t)j * HH);
#pragma unroll
    for (int i = 0; i < 64; i++) w[i] = wp[i];

    if (j < HH) s_h[j] = 0.f;
    float hreg = 0.f;

    long long tokbase = (long long)b * SS;
    int t0 = dir ? (SS - 1) : 0;
    long long gstr = dir ? -768 : 768;
    long long hstr = dir ? -256 : 256;

    const float* gp = g_gx + (tokbase + t0) * 768 + (long long)dir * G3 + j;
    float*       hp = g_hio + (tokbase + t0) * 256 + (long long)dir * HH + j;

    float gx_n1 = gp[0];
    gp += gstr;
    float gx_n2 = gp[0];
    __syncthreads();

    for (int tt = 0; tt < SS; tt++) {
        float gxv = gx_n1;
        gx_n1 = gx_n2;
        gp += gstr;
        if (tt + 2 < SS) gx_n2 = *gp;           // 2-step-ahead prefetch

        unsigned long long a0 = 0ull, a1 = 0ull;
        const ulonglong2* hv = (const ulonglong2*)s_h;
#pragma unroll
        for (int k = 0; k < 32; k++) {
            ulonglong2 hk = hv[k];               // LDS.128, warp-uniform broadcast
            a0 = ffma2(w[2 * k],     hk.x, a0);
            a1 = ffma2(w[2 * k + 1], hk.y, a1);
        }
        float2 f0 = unpk(a0), f1 = unpk(a1);
        float gh = (f0.x + f0.y) + (f1.x + f1.y) + bhh;

        if (j < 2 * HH) {
            s_b[j] = gh + gxv;                   // r,z rows: pre-added
        } else {
            s_b[j] = gh;                         // n rows: keep hn separate
            s_xn[j - 2 * HH] = gxv;
        }

        if (j < HH) {
            // gate warps: wait for all partials, then produce h
            asm volatile("bar.sync 1, 384;" ::: "memory");
            float r = sigf(s_b[j]);
            float z = sigf(s_b[HH + j]);
            float n = tanhfast(fmaf(r, s_b[2 * HH + j], s_xn[j]));
            hreg = fmaf(z, hreg - n, n);         // (1-z)*n + z*h
            s_h[j] = hreg;
            asm volatile("bar.sync 3, 128;" ::: "memory");   // gate-internal
            asm volatile("bar.arrive 2, 384;" ::: "memory"); // release consumers
            *hp = hreg;                          // STG off the critical path
            hp += hstr;
        } else {
            asm volatile("bar.arrive 1, 384;" ::: "memory"); // publish partial
            asm volatile("bar.sync 2, 384;" ::: "memory");   // wait for h
        }
    }
}

// ---------------- layer-1 GEMM via mma.sync (bf16 3-term split) ----------------
// R6-validated single-buffer version. C[262144x768] = A[262144x256]*W^T + bias.
// CTA tile M=128, N=256 (grid.y = 3), 8 warps as 2x4 (warp tile 64x64),
// K in 16 chunks of 16. acc += Ah*Bh + Ah*Bl + Al*Bh (fp32 accumulate).
#define ASTR 24          // smem row stride in bf16 elems (48B: aligned, no conflicts)

__global__ void __launch_bounds__(256, 1) k_gemm_tc(
    const float* __restrict__ Wf, const float* __restrict__ bf,
    const float* __restrict__ Wb, const float* __restrict__ bb) {
    __shared__ __align__(16) __nv_bfloat16 Ah[128][ASTR];
    __shared__ __align__(16) __nv_bfloat16 Al[128][ASTR];
    __shared__ __align__(16) __nv_bfloat16 Bh[256][ASTR];
    __shared__ __align__(16) __nv_bfloat16 Bl[256][ASTR];

    int tid = threadIdx.x, wid = tid >> 5, lane = tid & 31;
    long long m0 = (long long)blockIdx.x * 128;
    int n0 = blockIdx.y * 256;
    int wm = wid >> 2, wn = wid & 3;             // warp 64x64 tile at (wm*64, wn*64)

    uint32_t aoff = (uint32_t)(((wm * 64 + (lane & 15)) * ASTR + (lane >> 4) * 8) * 2);
    uint32_t boff = (uint32_t)(((wn * 64 + (lane & 7) + ((lane >> 4) << 3)) * ASTR
                                + ((lane >> 3) & 1) * 8) * 2);
    uint32_t ah_a = smem_u32(Ah) + aoff, al_a = smem_u32(Al) + aoff;
    uint32_t bh_a = smem_u32(Bh) + boff, bl_a = smem_u32(Bl) + boff;

    float acc[4][8][4];
#pragma unroll
    for (int i = 0; i < 4; i++)
#pragma unroll
        for (int jx = 0; jx < 8; jx++)
#pragma unroll
            for (int q = 0; q < 4; q++) acc[i][jx][q] = 0.f;

    float4 pA[2], pB[4];
#pragma unroll
    for (int i = 0; i < 2; i++) {
        int task = tid + i * 256, row = task >> 2, c4 = task & 3;
        pA[i] = *(const float4*)(g_hio + (m0 + row) * 256 + c4 * 4);
    }
#pragma unroll
    for (int i = 0; i < 4; i++) {
        int task = tid + i * 256, row = task >> 2, c4 = task & 3;
        int n = n0 + row;
        const float* src = (n < 384) ? (Wf + (size_t)n * 256)
                                     : (Wb + (size_t)(n - 384) * 256);
        pB[i] = *(const float4*)(src + c4 * 4);
    }

    for (int ck = 0; ck < 16; ck++) {
#pragma unroll
        for (int i = 0; i < 2; i++) {
            int task = tid + i * 256, row = task >> 2, c4 = task & 3;
            float4 v = pA[i];
            __nv_bfloat16 hx = __float2bfloat16(v.x), hy = __float2bfloat16(v.y);
            __nv_bfloat16 hz = __float2bfloat16(v.z), hw = __float2bfloat16(v.w);
            __nv_bfloat162 h01 = __halves2bfloat162(hx, hy);
            __nv_bfloat162 h23 = __halves2bfloat162(hz, hw);
            __nv_bfloat162 l01 = __halves2bfloat162(
                __float2bfloat16(v.x - __bfloat162float(hx)),
                __float2bfloat16(v.y - __bfloat162float(hy)));
            __nv_bfloat162 l23 = __halves2bfloat162(
                __float2bfloat16(v.z - __bfloat162float(hz)),
                __float2bfloat16(v.w - __bfloat162float(hw)));
            *(uint2*)&Ah[row][c4 * 4] = make_uint2(*(uint32_t*)&h01, *(uint32_t*)&h23);
            *(uint2*)&Al[row][c4 * 4] = make_uint2(*(uint32_t*)&l01, *(uint32_t*)&l23);
        }
#pragma unroll
        for (int i = 0; i < 4; i++) {
            int task = tid + i * 256, row = task >> 2, c4 = task & 3;
            float4 v = pB[i];
            __nv_bfloat16 hx = __float2bfloat16(v.x), hy = __float2bfloat16(v.y);
            __nv_bfloat16 hz = __float2bfloat16(v.z), hw = __float2bfloat16(v.w);
            __nv_bfloat162 h01 = __halves2bfloat162(hx, hy);
            __nv_bfloat162 h23 = __halves2bfloat162(hz, hw);
            __nv_bfloat162 l01 = __halves2bfloat162(
                __float2bfloat16(v.x - __bfloat162float(hx)),
                __float2bfloat16(v.y - __bfloat162float(hy)));
            __nv_bfloat162 l23 = __halves2bfloat162(
                __float2bfloat16(v.z - __bfloat162float(hz)),
                __float2bfloat16(v.w - __bfloat162float(hw)));
            *(uint2*)&Bh[row][c4 * 4] = make_uint2(*(uint32_t*)&h01, *(uint32_t*)&h23);
            *(uint2*)&Bl[row][c4 * 4] = make_uint2(*(uint32_t*)&l01, *(uint32_t*)&l23);
        }
        __syncthreads();

        if (ck + 1 < 16) {
            int kc = (ck + 1) * 16;
#pragma unroll
            for (int i = 0; i < 2; i++) {
                int task = tid + i * 256, row = task >> 2, c4 = task & 3;
                pA[i] = *(const float4*)(g_hio + (m0 + row) * 256 + kc + c4 * 4);
            }
#pragma unroll
            for (int i = 0; i < 4; i++) {
                int task = tid + i * 256, row = task >> 2, c4 = task & 3;
                int n = n0 + row;
                const float* src = (n < 384) ? (Wf + (size_t)n * 256)
                                             : (Wb + (size_t)(n - 384) * 256);
                pB[i] = *(const float4*)(src + kc + c4 * 4);
            }
        }

#pragma unroll
        for (int term = 0; term < 3; term++) {
            uint32_t aAddr = (term == 2) ? al_a : ah_a;
            uint32_t bAddr = (term == 1) ? bl_a : bh_a;
            uint32_t afr[4][4];
#pragma unroll
            for (int mf = 0; mf < 4; mf++)
                ldmx4(afr[mf][0], afr[mf][1], afr[mf][2], afr[mf][3],
                      aAddr + mf * (16 * ASTR * 2));
            uint32_t bfr[8][2];
#pragma unroll
            for (int p = 0; p < 4; p++) {
                uint32_t r0, r1, r2, r3;
                ldmx4(r0, r1, r2, r3, bAddr + p * (16 * ASTR * 2));
                bfr[2 * p][0] = r0; bfr[2 * p][1] = r1;
                bfr[2 * p + 1][0] = r2; bfr[2 * p + 1][1] = r3;
            }
#pragma unroll
            for (int mf = 0; mf < 4; mf++)
#pragma unroll
                for (int nf = 0; nf < 8; nf++)
                    mma_bf16(acc[mf][nf], afr[mf], bfr[nf]);
        }
        __syncthreads();
    }

    int g = lane >> 2, c2 = (lane & 3) * 2;
    float bias2[8][2];
#pragma unroll
    for (int nf = 0; nf < 8; nf++) {
        int col = n0 + wn * 64 + nf * 8 + c2;
        bias2[nf][0] = (col < 384) ? bf[col] : bb[col - 384];
        bias2[nf][1] = (col + 1 < 384) ? bf[col + 1] : bb[col + 1 - 384];
    }
#pragma unroll
    for (int mf = 0; mf < 4; mf++) {
        long long r0 = m0 + wm * 64 + mf * 16 + g;
#pragma unroll
        for (int nf = 0; nf < 8; nf++) {
            int col = n0 + wn * 64 + nf * 8 + c2;
            *(float2*)&g_gx[r0 * 768 + col] =
                make_float2(acc[mf][nf][0] + bias2[nf][0],
                            acc[mf][nf][1] + bias2[nf][1]);
            *(float2*)&g_gx[(r0 + 8) * 768 + col] =
                make_float2(acc[mf][nf][2] + bias2[nf][0],
                            acc[mf][nf][3] + bias2[nf][1]);
        }
    }
}

// ---------------- output head: logits = h1out @ wout^T + bout -----------------
__global__ void k_head(const float* __restrict__ wout,
                       const float* __restrict__ bout,
                       float* __restrict__ out) {
    int warp = threadIdx.x >> 5, lane = threadIdx.x & 31;
    long long token = (long long)blockIdx.x * 8 + warp;
    const float* hrow = g_hio + token * 256;
    float acc = 0.f;
#pragma unroll
    for (int i = 0; i < 8; i++) {
        int c = lane + i * 32;
        acc = fmaf(hrow[c], wout[c], acc);
    }
#pragma unroll
    for (int off = 16; off; off >>= 1)
        acc += __shfl_xor_sync(0xffffffffu, acc, off);
    if (lane == 0) out[token] = acc + bout[0];
}

// ---------------- launch ------------------------------------------------------
extern "C" void kernel_launch(void* const* d_in, const int* in_sizes, int n_in,
                              void* d_out, int out_size) {
    const float* x     = (const float*)d_in[0];
    const float* wih0f = (const float*)d_in[1];
    const float* whh0f = (const float*)d_in[2];
    const float* bih0f = (const float*)d_in[3];
    const float* bhh0f = (const float*)d_in[4];
    const float* wih0b = (const float*)d_in[5];
    const float* whh0b = (const float*)d_in[6];
    const float* bih0b = (const float*)d_in[7];
    const float* bhh0b = (const float*)d_in[8];
    const float* wih1f = (const float*)d_in[9];
    const float* whh1f = (const float*)d_in[10];
    const float* bih1f = (const float*)d_in[11];
    const float* bhh1f = (const float*)d_in[12];
    const float* wih1b = (const float*)d_in[13];
    const float* whh1b = (const float*)d_in[14];
    const float* bih1b = (const float*)d_in[15];
    const float* bhh1b = (const float*)d_in[16];
    const float* wout  = (const float*)d_in[17];
    const float* bout  = (const float*)d_in[18];
    float* out = (float*)d_out;

    k_gx0    <<<NTOK / 8, 768>>>(x, wih0f, bih0f, wih0b, bih0b);
    k_rec    <<<128, 384>>>(whh0f, bhh0f, whh0b, bhh0b);
    k_gemm_tc<<<dim3(2048, 3), 256>>>(wih1f, bih1f, wih1b, bih1b);
    k_rec    <<<128, 384>>>(whh1f, bhh1f, whh1b, bhh1b);
    k_head   <<<NTOK / 8, 256>>>(wout, bout, out);
}